// round 11
// baseline (speedup 1.0000x reference)
#include <cuda_runtime.h>
#include <cuda_bf16.h>
#include <cstdint>
#include <math.h>

#define NCTX   4096
#define DMODEL 2048
#define DHEAD  128

typedef __nv_bfloat16 bf16;

// ---------------- scratch (__device__ globals; no allocation allowed) -------
__device__ bf16 g_x_hi[NCTX * DMODEL],  g_x_lo[NCTX * DMODEL];
__device__ bf16 g_xT_hi[DMODEL * NCTX], g_xT_lo[DMODEL * NCTX];
__device__ bf16 g_Wq_hi[DHEAD * DMODEL], g_Wq_lo[DHEAD * DMODEL];
__device__ bf16 g_Wk_hi[DHEAD * DMODEL], g_Wk_lo[DHEAD * DMODEL];
__device__ bf16 g_W2_hi[DMODEL * DMODEL], g_W2_lo[DMODEL * DMODEL];
__device__ bf16 g_q_hi[NCTX * DHEAD], g_q_lo[NCTX * DHEAD];
__device__ bf16 g_k_hi[NCTX * DHEAD], g_k_lo[NCTX * DHEAD];
__device__ float g_S[(size_t)NCTX * NCTX];          // also holds q/k K-split partials early
__device__ bf16 g_P_hi[(size_t)NCTX * NCTX], g_P_lo[(size_t)NCTX * NCTX];
__device__ bf16 g_O1_hi[NCTX * DMODEL], g_O1_lo[NCTX * DMODEL];
__device__ int  g_done[NCTX / 128];                 // P@x row-block completion counters

// ---------------- helpers ----------------------------------------------------
__device__ __forceinline__ uint32_t smem_u32(const void* p) {
    uint32_t a;
    asm("{ .reg .u64 t; cvta.to.shared.u64 t, %1; cvt.u32.u64 %0, t; }" : "=r"(a) : "l"(p));
    return a;
}
__device__ __forceinline__ void cp16(uint32_t dst, const void* src) {
    asm volatile("cp.async.cg.shared.global [%0], [%1], 16;" :: "r"(dst), "l"(src) : "memory");
}
#define CP_COMMIT() asm volatile("cp.async.commit_group;" ::: "memory")
#define CP_WAIT2()  asm volatile("cp.async.wait_group 2;" ::: "memory")
#define CP_WAIT1()  asm volatile("cp.async.wait_group 1;" ::: "memory")
#define CP_WAIT0()  asm volatile("cp.async.wait_group 0;" ::: "memory")

__device__ __forceinline__ void ldsm4(uint32_t* r, uint32_t addr) {
    asm volatile("ldmatrix.sync.aligned.m8n8.x4.shared.b16 {%0,%1,%2,%3}, [%4];"
                 : "=r"(r[0]), "=r"(r[1]), "=r"(r[2]), "=r"(r[3]) : "r"(addr));
}
__device__ __forceinline__ void mma16816(float* c, const uint32_t* a, const uint32_t* b) {
    asm volatile("mma.sync.aligned.m16n8k16.row.col.f32.bf16.bf16.f32 "
                 "{%0,%1,%2,%3}, {%4,%5,%6,%7}, {%8,%9}, {%0,%1,%2,%3};"
                 : "+f"(c[0]), "+f"(c[1]), "+f"(c[2]), "+f"(c[3])
                 : "r"(a[0]), "r"(a[1]), "r"(a[2]), "r"(a[3]), "r"(b[0]), "r"(b[1]));
}

__device__ __forceinline__ void split1(float v, bf16& h, bf16& l) {
    h = __float2bfloat16(v);
    l = __float2bfloat16(v - __bfloat162float(h));
}
__device__ __forceinline__ uint32_t pack2(bf16 a, bf16 b) {
    return (uint32_t)__bfloat16_as_ushort(a) | ((uint32_t)__bfloat16_as_ushort(b) << 16);
}

// ---------------- SMEM layout ------------------------------------------------
// Per buffer: 4 tiles (Ah, Al, Bh, Bl), 128 rows x 64 bf16 (BK=64), padded to 72.
// Row stride = 144B = 36 words -> +4 banks/row: ldmatrix 8-row reads conflict-free.
#define LDT        72
#define TILE_B     (128 * LDT * 2)      // 18432 B
#define BUF_B      (4 * TILE_B)         // 73728 B
#define NSTAGE     3
#define SMEM_TOTAL (NSTAGE * BUF_B)     // 221184 B
#define STG_LD     132                  // epilogue stage row stride (floats)

// ---------------------------------------------------------------------------
// bf16 split-precision NT GEMM on mma.sync (m16n8k16), 8 warps, warp tile 32x64:
//   C[M,N] = (Ah+Al)[M,K] @ (Bh+Bl)[N,K]^T   (terms hh + hl + lh), fp32 accum.
// OUTM: 0 -> write fp32 C; 1 -> write bf16 hi/lo split (Ch, Cl).
// LOWER: 1D grid packs lower-triangle tiles, no dead CTAs.
// CAUSALK: K-limit (byd+1)*128; grid-y REVERSED so longest tiles launch first.
// QK: fused q/k projection with split-K=2 (bx bit1: Wq/Wk, bit0: K half).
// FUSED: single 1024-CTA launch covering P@x (bids 0..511, writes O1 hi/lo and
//   releases g_done[row]) and O1@W2^T (bids 512..1023, spins on g_done[row]==16
//   then writes fp32 C). Deadlock-free under in-order dispatch.
// ---------------------------------------------------------------------------
template <int OUTM, bool LOWER, bool CAUSALK, bool QK, bool FUSED>
__global__ void __launch_bounds__(256, 1)
gemm_mma(const bf16* __restrict__ Ah, const bf16* __restrict__ Al,
         const bf16* __restrict__ Bh, const bf16* __restrict__ Bl,
         const bf16* __restrict__ B2h, const bf16* __restrict__ B2l,
         const bf16* __restrict__ A2h, const bf16* __restrict__ A2l,
         float* __restrict__ C, bf16* __restrict__ Ch, bf16* __restrict__ Cl,
         int M, int N, int K, int K2, int* done)
{
    // ---- logical tile coordinates ----
    int bxd, byd;
    bool isW2 = false;
    if (FUSED) {
        int t = blockIdx.x;
        isW2 = (t >= 512);
        if (isW2) t -= 512;
        byd = 31 - (t >> 4);            // LPT: longest rows first
        bxd = t & 15;
    } else if (LOWER) {
        int t = blockIdx.x;
        int r = (int)((sqrtf(8.f * t + 1.f) - 1.f) * 0.5f);
        while ((r + 1) * (r + 2) / 2 <= t) ++r;
        while (r * (r + 1) / 2 > t) --r;
        byd = r;
        bxd = t - r * (r + 1) / 2;
    } else {
        bxd = blockIdx.x;
        byd = CAUSALK ? ((int)gridDim.y - 1 - (int)blockIdx.y) : (int)blockIdx.y;  // LPT
    }

    extern __shared__ char smem[];
    const uint32_t sbase = smem_u32(smem);
    const int tid  = threadIdx.x;
    const int lane = tid & 31;
    const int wid  = tid >> 5;
    const int wm   = wid & 3;        // 4 warps along M (32 rows each)
    const int wn   = wid >> 2;       // 2 warps along N (64 cols each)

    const bf16* uAh = Ah;
    const bf16* uAl = Al;
    const bf16* uBh = Bh;
    const bf16* uBl = Bl;
    int Kst = K;                     // operand row stride (elements)
    int kOff = 0;
    int kLen = CAUSALK ? min(K, (byd + 1) * 128) : K;
    float* Cuse = C;
    int colBase = bxd * 128;
    int bRowBase = bxd * 128;

    if (FUSED) {
        if (isW2) {
            uAh = A2h; uAl = A2l; uBh = B2h; uBl = B2l;
            Kst = K2; kLen = K2;
            if (tid == 0) {
                while (atomicAdd(done + byd, 0) < 16) __nanosleep(200);
            }
            __syncthreads();
            __threadfence();
        } else {
            kLen = (byd + 1) * 128;  // causal K-limit, K = NCTX
        }
    }
    if (QK) {
        if (bxd >> 1) { uBh = B2h; uBl = B2l; }
        kOff = (bxd & 1) * (K >> 1);
        kLen = K >> 1;
        Cuse = C + (size_t)bxd * ((size_t)M * N);
        colBase = 0;
        bRowBase = 0;
    }

    const bf16* tbase[4] = { uAh + (size_t)byd * 128 * Kst, uAl + (size_t)byd * 128 * Kst,
                             uBh + (size_t)bRowBase * Kst,  uBl + (size_t)bRowBase * Kst };

    const int nc = kLen >> 6;        // chunks of 64

    float acc[2][8][4];
    #pragma unroll
    for (int i = 0; i < 2; ++i)
        #pragma unroll
        for (int j = 0; j < 8; ++j)
            #pragma unroll
            for (int r = 0; r < 4; ++r) acc[i][j][r] = 0.f;

    // ---- async loader for one 64-wide K chunk into stage (c % 3) ----
    auto load_chunk = [&](int c) {
        const int b = c % NSTAGE;
        const int k0 = kOff + (c << 6);
        #pragma unroll
        for (int i = 0; i < 16; ++i) {
            const int t = i >> 2;
            const int v = ((i & 3) << 8) + tid;     // 0..1023
            const int r = v >> 3, s = v & 7;
            const bf16* src = tbase[t] + (size_t)r * Kst + k0 + s * 8;
            uint32_t dst = sbase + b * BUF_B + t * TILE_B + (r * LDT + s * 8) * 2;
            cp16(dst, src);
        }
        CP_COMMIT();
    };

    // ldmatrix lane addressing (element offsets)
    const int a_row = ((lane >> 3) & 1) * 8 + (lane & 7);
    const int a_ko  = (lane >> 4) * 8;
    const int b_row = (lane >> 4) * 8 + (lane & 7);
    const int b_ko  = ((lane >> 3) & 1) * 8;

    load_chunk(0);
    if (nc > 1) load_chunk(1);

    for (int c = 0; c < nc; ++c) {
        if (c + 2 < nc) { load_chunk(c + 2); CP_WAIT2(); }
        else if (c + 1 < nc) { CP_WAIT1(); }
        else { CP_WAIT0(); }
        __syncthreads();

        const uint32_t bufb = sbase + (c % NSTAGE) * BUF_B;
        #pragma unroll
        for (int ks = 0; ks < 4; ++ks) {
            uint32_t ah[2][4], al[2][4], bh[8][2], bl[8][2];
            #pragma unroll
            for (int mi = 0; mi < 2; ++mi) {
                int row = wm * 32 + mi * 16 + a_row;
                int ko  = ks * 16 + a_ko;
                ldsm4(ah[mi], bufb + 0 * TILE_B + (row * LDT + ko) * 2);
                ldsm4(al[mi], bufb + 1 * TILE_B + (row * LDT + ko) * 2);
            }
            #pragma unroll
            for (int nj = 0; nj < 4; ++nj) {
                int row = wn * 64 + nj * 16 + b_row;
                int ko  = ks * 16 + b_ko;
                uint32_t r4[4];
                ldsm4(r4, bufb + 2 * TILE_B + (row * LDT + ko) * 2);
                bh[nj * 2][0] = r4[0]; bh[nj * 2][1] = r4[1];
                bh[nj * 2 + 1][0] = r4[2]; bh[nj * 2 + 1][1] = r4[3];
                ldsm4(r4, bufb + 3 * TILE_B + (row * LDT + ko) * 2);
                bl[nj * 2][0] = r4[0]; bl[nj * 2][1] = r4[1];
                bl[nj * 2 + 1][0] = r4[2]; bl[nj * 2 + 1][1] = r4[3];
            }
            // term-major: all hh, then all hl, then all lh (RAW distance = 16)
            #pragma unroll
            for (int mi = 0; mi < 2; ++mi)
                #pragma unroll
                for (int n = 0; n < 8; ++n)
                    mma16816(acc[mi][n], ah[mi], bh[n]);   // hh
            #pragma unroll
            for (int mi = 0; mi < 2; ++mi)
                #pragma unroll
                for (int n = 0; n < 8; ++n)
                    mma16816(acc[mi][n], ah[mi], bl[n]);   // hl
            #pragma unroll
            for (int mi = 0; mi < 2; ++mi)
                #pragma unroll
                for (int n = 0; n < 8; ++n)
                    mma16816(acc[mi][n], al[mi], bh[n]);   // lh
        }
        __syncthreads();
    }

    // ---- epilogue: stage fragments through smem, emit coalesced rows ----
    float* stage = reinterpret_cast<float*>(smem);
    #pragma unroll
    for (int mi = 0; mi < 2; ++mi) {
        #pragma unroll
        for (int nt = 0; nt < 8; ++nt) {
            int r0 = wm * 32 + mi * 16 + (lane >> 2);
            int cc = wn * 64 + nt * 8 + (lane & 3) * 2;
            float* a4 = acc[mi][nt];
            *reinterpret_cast<float2*>(&stage[r0 * STG_LD + cc]) = make_float2(a4[0], a4[1]);
            *reinterpret_cast<float2*>(&stage[(r0 + 8) * STG_LD + cc]) = make_float2(a4[2], a4[3]);
        }
    }
    __syncthreads();

    {
        const int row = tid >> 1;
        const int ch  = (tid & 1) * 64;
        const size_t grow = (size_t)(byd * 128 + row);
        const float* srow = &stage[row * STG_LD + ch];
        const bool outF32 = FUSED ? isW2 : (OUTM == 0);
        if (outF32) {
            float* dst = Cuse + grow * N + colBase + ch;
            #pragma unroll
            for (int i = 0; i < 16; ++i)
                *reinterpret_cast<float4*>(dst + i * 4) =
                    *reinterpret_cast<const float4*>(srow + i * 4);
        } else {
            bf16* dh = Ch + grow * N + colBase + ch;
            bf16* dl = Cl + grow * N + colBase + ch;
            #pragma unroll
            for (int i = 0; i < 16; ++i) {
                float4 v = *reinterpret_cast<const float4*>(srow + i * 4);
                bf16 h0, l0, h1, l1, h2, l2, h3, l3;
                split1(v.x, h0, l0); split1(v.y, h1, l1);
                split1(v.z, h2, l2); split1(v.w, h3, l3);
                *reinterpret_cast<uint2*>(dh + i * 4) =
                    make_uint2(pack2(h0, h1), pack2(h2, h3));
                *reinterpret_cast<uint2*>(dl + i * 4) =
                    make_uint2(pack2(l0, l1), pack2(l2, l3));
            }
        }
    }

    if (FUSED && !isW2) {
        __threadfence();          // make O1 stores visible before release
        __syncthreads();          // all threads' stores fenced
        if (tid == 0) atomicAdd(done + byd, 1);
    }
}

// ---------------- split / transpose / reduce / softmax -----------------------
__global__ void __launch_bounds__(256) split2(const float* __restrict__ in,
                                              bf16* __restrict__ hi, bf16* __restrict__ lo,
                                              int n4)
{
    int i = blockIdx.x * 256 + threadIdx.x;
    if (i >= n4) return;
    float4 v = reinterpret_cast<const float4*>(in)[i];
    bf16 h0, l0, h1, l1, h2, l2, h3, l3;
    split1(v.x, h0, l0); split1(v.y, h1, l1); split1(v.z, h2, l2); split1(v.w, h3, l3);
    reinterpret_cast<uint2*>(hi)[i] = make_uint2(pack2(h0, h1), pack2(h2, h3));
    reinterpret_cast<uint2*>(lo)[i] = make_uint2(pack2(l0, l1), pack2(l2, l3));
}

// parts: [4][NCTX*DHEAD] fp32 = {q half0, q half1, k half0, k half1}
__global__ void __launch_bounds__(256) reduce_split(const float* __restrict__ parts,
                                                    bf16* __restrict__ qh, bf16* __restrict__ ql,
                                                    bf16* __restrict__ kh, bf16* __restrict__ kl)
{
    const int o = blockIdx.y;                 // 0 = q, 1 = k
    const int i = blockIdx.x * 256 + threadIdx.x;   // float4 index
    const int n4 = NCTX * DHEAD / 4;
    if (i >= n4) return;
    const float4* p0 = reinterpret_cast<const float4*>(parts + (size_t)o * 2 * NCTX * DHEAD);
    const float4* p1 = p0 + n4;
    float4 a = p0[i], b = p1[i];
    float4 s = make_float4(a.x + b.x, a.y + b.y, a.z + b.z, a.w + b.w);
    bf16 h0, l0, h1, l1, h2, l2, h3, l3;
    split1(s.x, h0, l0); split1(s.y, h1, l1); split1(s.z, h2, l2); split1(s.w, h3, l3);
    bf16* hi = o ? kh : qh;
    bf16* lo = o ? kl : ql;
    reinterpret_cast<uint2*>(hi)[i] = make_uint2(pack2(h0, h1), pack2(h2, h3));
    reinterpret_cast<uint2*>(lo)[i] = make_uint2(pack2(l0, l1), pack2(l2, l3));
}

__global__ void __launch_bounds__(256) transpose_split(const float* __restrict__ in,  // [R, Ccols]
                                                       bf16* __restrict__ tHi, bf16* __restrict__ tLo,
                                                       int R, int Ccols)
{
    __shared__ float t[32][33];
    int c0 = blockIdx.x * 32, r0 = blockIdx.y * 32;
    int tx = threadIdx.x & 31, ty = threadIdx.x >> 5;   // 32 x 8
    #pragma unroll
    for (int j = 0; j < 4; ++j)
        t[ty + 8 * j][tx] = in[(size_t)(r0 + ty + 8 * j) * Ccols + c0 + tx];
    __syncthreads();
    #pragma unroll
    for (int j = 0; j < 4; ++j) {
        float v = t[tx][ty + 8 * j];
        bf16 h, l; split1(v, h, l);
        size_t o = (size_t)(c0 + ty + 8 * j) * R + r0 + tx;
        tHi[o] = h; tLo[o] = l;
    }
}

__device__ __forceinline__ float warpMax(float v) {
    #pragma unroll
    for (int o = 16; o > 0; o >>= 1) v = fmaxf(v, __shfl_xor_sync(0xffffffffu, v, o));
    return v;
}
__device__ __forceinline__ float warpSum(float v) {
    #pragma unroll
    for (int o = 16; o > 0; o >>= 1) v += __shfl_xor_sync(0xffffffffu, v, o);
    return v;
}

// Register-resident causal row softmax: S read ONCE (4 float4/thread), exp
// computed once, P written as hi/lo bf16 (zero-padded to row's 128 boundary).
__global__ void __launch_bounds__(256) softmax_split(const float* __restrict__ S,
                                                     bf16* __restrict__ Ph, bf16* __restrict__ Pl)
{
    const int row    = blockIdx.x;
    const int len    = row + 1;
    const int padLen = (row & ~127) + 128;
    const int nf4    = padLen >> 2;            // float4s to produce (multiple of 32)
    const float* Sr = S + (size_t)row * NCTX;
    bf16* PhR = Ph + (size_t)row * NCTX;
    bf16* PlR = Pl + (size_t)row * NCTX;

    __shared__ float sh[8];
    const int lane = threadIdx.x & 31;
    const int wid  = threadIdx.x >> 5;

    // load row into registers (up to 4 float4 per thread), tracking local max
    float v[4][4];
    float m = -3.4e38f;
    #pragma unroll
    for (int j = 0; j < 4; ++j) {
        const int f4 = threadIdx.x + j * 256;
        const int base = f4 * 4;
        if (f4 < nf4 && base < len) {
            float4 t = *reinterpret_cast<const float4*>(Sr + base);
            v[j][0] = (base + 0 < len) ? t.x : -3.4e38f;
            v[j][1] = (base + 1 < len) ? t.y : -3.4e38f;
            v[j][2] = (base + 2 < len) ? t.z : -3.4e38f;
            v[j][3] = (base + 3 < len) ? t.w : -3.4e38f;
            m = fmaxf(m, fmaxf(fmaxf(v[j][0], v[j][1]), fmaxf(v[j][2], v[j][3])));
        } else {
            v[j][0] = v[j][1] = v[j][2] = v[j][3] = -3.4e38f;
        }
    }
    m = warpMax(m);
    if (lane == 0) sh[wid] = m;
    __syncthreads();
    m = warpMax(lane < 8 ? sh[lane] : -3.4e38f);

    // exp in registers (once), local sum
    float s = 0.f;
    #pragma unroll
    for (int j = 0; j < 4; ++j)
        #pragma unroll
        for (int e = 0; e < 4; ++e) {
            float p = (v[j][e] > -3.0e38f) ? __expf(v[j][e] - m) : 0.f;
            v[j][e] = p;
            s += p;
        }
    s = warpSum(s);
    __syncthreads();
    if (lane == 0) sh[wid] = s;
    __syncthreads();
    s = warpSum(lane < 8 ? sh[lane] : 0.f);

    const float inv = 1.f / s;
    #pragma unroll
    for (int j = 0; j < 4; ++j) {
        const int f4 = threadIdx.x + j * 256;
        if (f4 < nf4) {
            bf16 h0, l0, h1, l1, h2, l2, h3, l3;
            split1(v[j][0] * inv, h0, l0); split1(v[j][1] * inv, h1, l1);
            split1(v[j][2] * inv, h2, l2); split1(v[j][3] * inv, h3, l3);
            *reinterpret_cast<uint2*>(PhR + f4 * 4) = make_uint2(pack2(h0, h1), pack2(h2, h3));
            *reinterpret_cast<uint2*>(PlR + f4 * 4) = make_uint2(pack2(l0, l1), pack2(l2, l3));
        }
    }
}

// ---------------------------------------------------------------------------
extern "C" void kernel_launch(void* const* d_in, const int* in_sizes, int n_in,
                              void* d_out, int out_size)
{
    const float* x  = (const float*)d_in[0];
    const float* Wk = (const float*)d_in[1];
    const float* Wq = (const float*)d_in[2];
    const float* W2 = (const float*)d_in[3];
    float* out = (float*)d_out;

    bf16 *x_hi, *x_lo, *xT_hi, *xT_lo, *Wq_hi, *Wq_lo, *Wk_hi, *Wk_lo, *W2_hi, *W2_lo;
    bf16 *q_hi, *q_lo, *k_hi, *k_lo, *P_hi, *P_lo, *O1_hi, *O1_lo;
    float* S;
    int* done;
    cudaGetSymbolAddress((void**)&x_hi,  g_x_hi);  cudaGetSymbolAddress((void**)&x_lo,  g_x_lo);
    cudaGetSymbolAddress((void**)&xT_hi, g_xT_hi); cudaGetSymbolAddress((void**)&xT_lo, g_xT_lo);
    cudaGetSymbolAddress((void**)&Wq_hi, g_Wq_hi); cudaGetSymbolAddress((void**)&Wq_lo, g_Wq_lo);
    cudaGetSymbolAddress((void**)&Wk_hi, g_Wk_hi); cudaGetSymbolAddress((void**)&Wk_lo, g_Wk_lo);
    cudaGetSymbolAddress((void**)&W2_hi, g_W2_hi); cudaGetSymbolAddress((void**)&W2_lo, g_W2_lo);
    cudaGetSymbolAddress((void**)&q_hi,  g_q_hi);  cudaGetSymbolAddress((void**)&q_lo,  g_q_lo);
    cudaGetSymbolAddress((void**)&k_hi,  g_k_hi);  cudaGetSymbolAddress((void**)&k_lo,  g_k_lo);
    cudaGetSymbolAddress((void**)&P_hi,  g_P_hi);  cudaGetSymbolAddress((void**)&P_lo,  g_P_lo);
    cudaGetSymbolAddress((void**)&O1_hi, g_O1_hi); cudaGetSymbolAddress((void**)&O1_lo, g_O1_lo);
    cudaGetSymbolAddress((void**)&S, g_S);
    cudaGetSymbolAddress((void**)&done, g_done);

    cudaFuncSetAttribute(gemm_mma<0, false, false, true, false>,
                         cudaFuncAttributeMaxDynamicSharedMemorySize, SMEM_TOTAL);
    cudaFuncSetAttribute(gemm_mma<0, true, false, false, false>,
                         cudaFuncAttributeMaxDynamicSharedMemorySize, SMEM_TOTAL);
    cudaFuncSetAttribute(gemm_mma<1, false, false, false, true>,
                         cudaFuncAttributeMaxDynamicSharedMemorySize, SMEM_TOTAL);

    // split inputs to bf16 hi/lo (+ transposed x for the P@x NT GEMM)
    split2<<<(NCTX * DMODEL / 4 + 255) / 256, 256>>>(x, x_hi, x_lo, NCTX * DMODEL / 4);
    split2<<<(DHEAD * DMODEL / 4 + 255) / 256, 256>>>(Wq, Wq_hi, Wq_lo, DHEAD * DMODEL / 4);
    split2<<<(DHEAD * DMODEL / 4 + 255) / 256, 256>>>(Wk, Wk_hi, Wk_lo, DHEAD * DMODEL / 4);
    split2<<<(DMODEL * DMODEL / 4 + 255) / 256, 256>>>(W2, W2_hi, W2_lo, DMODEL * DMODEL / 4);
    transpose_split<<<dim3(DMODEL / 32, NCTX / 32), 256>>>(x, xT_hi, xT_lo, NCTX, DMODEL);

    // 1) fused q/k projection, split-K=2 -> fp32 partials in S scratch, then reduce+split
    gemm_mma<0, false, false, true, false><<<dim3(4, NCTX / 128), 256, SMEM_TOTAL>>>(
        x_hi, x_lo, Wq_hi, Wq_lo, Wk_hi, Wk_lo, nullptr, nullptr,
        S, nullptr, nullptr, NCTX, DHEAD, DMODEL, 0, nullptr);
    reduce_split<<<dim3(NCTX * DHEAD / 4 / 256, 2), 256>>>(S, q_hi, q_lo, k_hi, k_lo);

    // 2) S = q @ k^T -- packed lower-triangle 1D grid (528 CTAs, no dead blocks)
    gemm_mma<0, true, false, false, false><<<dim3(NCTX / 128 * (NCTX / 128 + 1) / 2, 1), 256, SMEM_TOTAL>>>(
        q_hi, q_lo, k_hi, k_lo, nullptr, nullptr, nullptr, nullptr,
        S, nullptr, nullptr, NCTX, NCTX, DHEAD, 0, nullptr);

    // 3) causal softmax (register-resident, single S read) -> P hi/lo
    softmax_split<<<NCTX, 256>>>(S, P_hi, P_lo);

    // 4+5) FUSED: P@x (bids 0..511 -> O1 hi/lo + release) and O1@W2^T (bids
    //      512..1023, spin on row completion -> fp32 out), one 1024-CTA launch.
    cudaMemsetAsync(done, 0, (NCTX / 128) * sizeof(int));
    gemm_mma<1, false, false, false, true><<<dim3(1024, 1), 256, SMEM_TOTAL>>>(
        P_hi, P_lo, xT_hi, xT_lo, W2_hi, W2_lo, O1_hi, O1_lo,
        out, O1_hi, O1_lo, NCTX, DMODEL, NCTX, DMODEL, done);
}

// round 12
// speedup vs baseline: 1.5365x; 1.5365x over previous
#include <cuda_runtime.h>
#include <cuda_bf16.h>
#include <cstdint>
#include <math.h>

#define NCTX   4096
#define DMODEL 2048
#define DHEAD  128
#define REBENCH_TAG 12   // R12: re-measurement of R11 (suspected throttled run)

typedef __nv_bfloat16 bf16;

// ---------------- scratch (__device__ globals; no allocation allowed) -------
__device__ bf16 g_x_hi[NCTX * DMODEL],  g_x_lo[NCTX * DMODEL];
__device__ bf16 g_xT_hi[DMODEL * NCTX], g_xT_lo[DMODEL * NCTX];
__device__ bf16 g_Wq_hi[DHEAD * DMODEL], g_Wq_lo[DHEAD * DMODEL];
__device__ bf16 g_Wk_hi[DHEAD * DMODEL], g_Wk_lo[DHEAD * DMODEL];
__device__ bf16 g_W2_hi[DMODEL * DMODEL], g_W2_lo[DMODEL * DMODEL];
__device__ bf16 g_q_hi[NCTX * DHEAD], g_q_lo[NCTX * DHEAD];
__device__ bf16 g_k_hi[NCTX * DHEAD], g_k_lo[NCTX * DHEAD];
__device__ float g_S[(size_t)NCTX * NCTX];          // also holds q/k K-split partials early
__device__ bf16 g_P_hi[(size_t)NCTX * NCTX], g_P_lo[(size_t)NCTX * NCTX];
__device__ bf16 g_O1_hi[NCTX * DMODEL], g_O1_lo[NCTX * DMODEL];
__device__ int  g_done[NCTX / 128];                 // P@x row-block completion counters

// ---------------- helpers ----------------------------------------------------
__device__ __forceinline__ uint32_t smem_u32(const void* p) {
    uint32_t a;
    asm("{ .reg .u64 t; cvta.to.shared.u64 t, %1; cvt.u32.u64 %0, t; }" : "=r"(a) : "l"(p));
    return a;
}
__device__ __forceinline__ void cp16(uint32_t dst, const void* src) {
    asm volatile("cp.async.cg.shared.global [%0], [%1], 16;" :: "r"(dst), "l"(src) : "memory");
}
#define CP_COMMIT() asm volatile("cp.async.commit_group;" ::: "memory")
#define CP_WAIT2()  asm volatile("cp.async.wait_group 2;" ::: "memory")
#define CP_WAIT1()  asm volatile("cp.async.wait_group 1;" ::: "memory")
#define CP_WAIT0()  asm volatile("cp.async.wait_group 0;" ::: "memory")

__device__ __forceinline__ void ldsm4(uint32_t* r, uint32_t addr) {
    asm volatile("ldmatrix.sync.aligned.m8n8.x4.shared.b16 {%0,%1,%2,%3}, [%4];"
                 : "=r"(r[0]), "=r"(r[1]), "=r"(r[2]), "=r"(r[3]) : "r"(addr));
}
__device__ __forceinline__ void mma16816(float* c, const uint32_t* a, const uint32_t* b) {
    asm volatile("mma.sync.aligned.m16n8k16.row.col.f32.bf16.bf16.f32 "
                 "{%0,%1,%2,%3}, {%4,%5,%6,%7}, {%8,%9}, {%0,%1,%2,%3};"
                 : "+f"(c[0]), "+f"(c[1]), "+f"(c[2]), "+f"(c[3])
                 : "r"(a[0]), "r"(a[1]), "r"(a[2]), "r"(a[3]), "r"(b[0]), "r"(b[1]));
}

__device__ __forceinline__ void split1(float v, bf16& h, bf16& l) {
    h = __float2bfloat16(v);
    l = __float2bfloat16(v - __bfloat162float(h));
}
__device__ __forceinline__ uint32_t pack2(bf16 a, bf16 b) {
    return (uint32_t)__bfloat16_as_ushort(a) | ((uint32_t)__bfloat16_as_ushort(b) << 16);
}

// ---------------- SMEM layout ------------------------------------------------
// Per buffer: 4 tiles (Ah, Al, Bh, Bl), 128 rows x 64 bf16 (BK=64), padded to 72.
// Row stride = 144B = 36 words -> +4 banks/row: ldmatrix 8-row reads conflict-free.
#define LDT        72
#define TILE_B     (128 * LDT * 2)      // 18432 B
#define BUF_B      (4 * TILE_B)         // 73728 B
#define NSTAGE     3
#define SMEM_TOTAL (NSTAGE * BUF_B)     // 221184 B
#define STG_LD     132                  // epilogue stage row stride (floats)

// ---------------------------------------------------------------------------
// bf16 split-precision NT GEMM on mma.sync (m16n8k16), 8 warps, warp tile 32x64:
//   C[M,N] = (Ah+Al)[M,K] @ (Bh+Bl)[N,K]^T   (terms hh + hl + lh), fp32 accum.
// OUTM: 0 -> write fp32 C; 1 -> write bf16 hi/lo split (Ch, Cl).
// LOWER: 1D grid packs lower-triangle tiles, no dead CTAs.
// CAUSALK: K-limit (byd+1)*128; grid-y REVERSED so longest tiles launch first.
// QK: fused q/k projection with split-K=2 (bx bit1: Wq/Wk, bit0: K half).
// FUSED: single 1024-CTA launch covering P@x (bids 0..511, writes O1 hi/lo and
//   releases g_done[row]) and O1@W2^T (bids 512..1023, spins on g_done[row]==16
//   then writes fp32 C). Deadlock-free under in-order dispatch.
// ---------------------------------------------------------------------------
template <int OUTM, bool LOWER, bool CAUSALK, bool QK, bool FUSED>
__global__ void __launch_bounds__(256, 1)
gemm_mma(const bf16* __restrict__ Ah, const bf16* __restrict__ Al,
         const bf16* __restrict__ Bh, const bf16* __restrict__ Bl,
         const bf16* __restrict__ B2h, const bf16* __restrict__ B2l,
         const bf16* __restrict__ A2h, const bf16* __restrict__ A2l,
         float* __restrict__ C, bf16* __restrict__ Ch, bf16* __restrict__ Cl,
         int M, int N, int K, int K2, int* done)
{
    // ---- logical tile coordinates ----
    int bxd, byd;
    bool isW2 = false;
    if (FUSED) {
        int t = blockIdx.x;
        isW2 = (t >= 512);
        if (isW2) t -= 512;
        byd = 31 - (t >> 4);            // LPT: longest rows first
        bxd = t & 15;
    } else if (LOWER) {
        int t = blockIdx.x;
        int r = (int)((sqrtf(8.f * t + 1.f) - 1.f) * 0.5f);
        while ((r + 1) * (r + 2) / 2 <= t) ++r;
        while (r * (r + 1) / 2 > t) --r;
        byd = r;
        bxd = t - r * (r + 1) / 2;
    } else {
        bxd = blockIdx.x;
        byd = CAUSALK ? ((int)gridDim.y - 1 - (int)blockIdx.y) : (int)blockIdx.y;  // LPT
    }

    extern __shared__ char smem[];
    const uint32_t sbase = smem_u32(smem);
    const int tid  = threadIdx.x;
    const int lane = tid & 31;
    const int wid  = tid >> 5;
    const int wm   = wid & 3;        // 4 warps along M (32 rows each)
    const int wn   = wid >> 2;       // 2 warps along N (64 cols each)

    const bf16* uAh = Ah;
    const bf16* uAl = Al;
    const bf16* uBh = Bh;
    const bf16* uBl = Bl;
    int Kst = K;                     // operand row stride (elements)
    int kOff = 0;
    int kLen = CAUSALK ? min(K, (byd + 1) * 128) : K;
    float* Cuse = C;
    int colBase = bxd * 128;
    int bRowBase = bxd * 128;

    if (FUSED) {
        if (isW2) {
            uAh = A2h; uAl = A2l; uBh = B2h; uBl = B2l;
            Kst = K2; kLen = K2;
            if (tid == 0) {
                while (atomicAdd(done + byd, 0) < 16) __nanosleep(200);
            }
            __syncthreads();
            __threadfence();
        } else {
            kLen = (byd + 1) * 128;  // causal K-limit, K = NCTX
        }
    }
    if (QK) {
        if (bxd >> 1) { uBh = B2h; uBl = B2l; }
        kOff = (bxd & 1) * (K >> 1);
        kLen = K >> 1;
        Cuse = C + (size_t)bxd * ((size_t)M * N);
        colBase = 0;
        bRowBase = 0;
    }

    const bf16* tbase[4] = { uAh + (size_t)byd * 128 * Kst, uAl + (size_t)byd * 128 * Kst,
                             uBh + (size_t)bRowBase * Kst,  uBl + (size_t)bRowBase * Kst };

    const int nc = kLen >> 6;        // chunks of 64

    float acc[2][8][4];
    #pragma unroll
    for (int i = 0; i < 2; ++i)
        #pragma unroll
        for (int j = 0; j < 8; ++j)
            #pragma unroll
            for (int r = 0; r < 4; ++r) acc[i][j][r] = 0.f;

    // ---- async loader for one 64-wide K chunk into stage (c % 3) ----
    auto load_chunk = [&](int c) {
        const int b = c % NSTAGE;
        const int k0 = kOff + (c << 6);
        #pragma unroll
        for (int i = 0; i < 16; ++i) {
            const int t = i >> 2;
            const int v = ((i & 3) << 8) + tid;     // 0..1023
            const int r = v >> 3, s = v & 7;
            const bf16* src = tbase[t] + (size_t)r * Kst + k0 + s * 8;
            uint32_t dst = sbase + b * BUF_B + t * TILE_B + (r * LDT + s * 8) * 2;
            cp16(dst, src);
        }
        CP_COMMIT();
    };

    // ldmatrix lane addressing (element offsets)
    const int a_row = ((lane >> 3) & 1) * 8 + (lane & 7);
    const int a_ko  = (lane >> 4) * 8;
    const int b_row = (lane >> 4) * 8 + (lane & 7);
    const int b_ko  = ((lane >> 3) & 1) * 8;

    load_chunk(0);
    if (nc > 1) load_chunk(1);

    for (int c = 0; c < nc; ++c) {
        if (c + 2 < nc) { load_chunk(c + 2); CP_WAIT2(); }
        else if (c + 1 < nc) { CP_WAIT1(); }
        else { CP_WAIT0(); }
        __syncthreads();

        const uint32_t bufb = sbase + (c % NSTAGE) * BUF_B;
        #pragma unroll
        for (int ks = 0; ks < 4; ++ks) {
            uint32_t ah[2][4], al[2][4], bh[8][2], bl[8][2];
            #pragma unroll
            for (int mi = 0; mi < 2; ++mi) {
                int row = wm * 32 + mi * 16 + a_row;
                int ko  = ks * 16 + a_ko;
                ldsm4(ah[mi], bufb + 0 * TILE_B + (row * LDT + ko) * 2);
                ldsm4(al[mi], bufb + 1 * TILE_B + (row * LDT + ko) * 2);
            }
            #pragma unroll
            for (int nj = 0; nj < 4; ++nj) {
                int row = wn * 64 + nj * 16 + b_row;
                int ko  = ks * 16 + b_ko;
                uint32_t r4[4];
                ldsm4(r4, bufb + 2 * TILE_B + (row * LDT + ko) * 2);
                bh[nj * 2][0] = r4[0]; bh[nj * 2][1] = r4[1];
                bh[nj * 2 + 1][0] = r4[2]; bh[nj * 2 + 1][1] = r4[3];
                ldsm4(r4, bufb + 3 * TILE_B + (row * LDT + ko) * 2);
                bl[nj * 2][0] = r4[0]; bl[nj * 2][1] = r4[1];
                bl[nj * 2 + 1][0] = r4[2]; bl[nj * 2 + 1][1] = r4[3];
            }
            // term-major: all hh, then all hl, then all lh (RAW distance = 16)
            #pragma unroll
            for (int mi = 0; mi < 2; ++mi)
                #pragma unroll
                for (int n = 0; n < 8; ++n)
                    mma16816(acc[mi][n], ah[mi], bh[n]);   // hh
            #pragma unroll
            for (int mi = 0; mi < 2; ++mi)
                #pragma unroll
                for (int n = 0; n < 8; ++n)
                    mma16816(acc[mi][n], ah[mi], bl[n]);   // hl
            #pragma unroll
            for (int mi = 0; mi < 2; ++mi)
                #pragma unroll
                for (int n = 0; n < 8; ++n)
                    mma16816(acc[mi][n], al[mi], bh[n]);   // lh
        }
        __syncthreads();
    }

    // ---- epilogue: stage fragments through smem, emit coalesced rows ----
    float* stage = reinterpret_cast<float*>(smem);
    #pragma unroll
    for (int mi = 0; mi < 2; ++mi) {
        #pragma unroll
        for (int nt = 0; nt < 8; ++nt) {
            int r0 = wm * 32 + mi * 16 + (lane >> 2);
            int cc = wn * 64 + nt * 8 + (lane & 3) * 2;
            float* a4 = acc[mi][nt];
            *reinterpret_cast<float2*>(&stage[r0 * STG_LD + cc]) = make_float2(a4[0], a4[1]);
            *reinterpret_cast<float2*>(&stage[(r0 + 8) * STG_LD + cc]) = make_float2(a4[2], a4[3]);
        }
    }
    __syncthreads();

    {
        const int row = tid >> 1;
        const int ch  = (tid & 1) * 64;
        const size_t grow = (size_t)(byd * 128 + row);
        const float* srow = &stage[row * STG_LD + ch];
        const bool outF32 = FUSED ? isW2 : (OUTM == 0);
        if (outF32) {
            float* dst = Cuse + grow * N + colBase + ch;
            #pragma unroll
            for (int i = 0; i < 16; ++i)
                *reinterpret_cast<float4*>(dst + i * 4) =
                    *reinterpret_cast<const float4*>(srow + i * 4);
        } else {
            bf16* dh = Ch + grow * N + colBase + ch;
            bf16* dl = Cl + grow * N + colBase + ch;
            #pragma unroll
            for (int i = 0; i < 16; ++i) {
                float4 v = *reinterpret_cast<const float4*>(srow + i * 4);
                bf16 h0, l0, h1, l1, h2, l2, h3, l3;
                split1(v.x, h0, l0); split1(v.y, h1, l1);
                split1(v.z, h2, l2); split1(v.w, h3, l3);
                *reinterpret_cast<uint2*>(dh + i * 4) =
                    make_uint2(pack2(h0, h1), pack2(h2, h3));
                *reinterpret_cast<uint2*>(dl + i * 4) =
                    make_uint2(pack2(l0, l1), pack2(l2, l3));
            }
        }
    }

    if (FUSED && !isW2) {
        __threadfence();          // make O1 stores visible before release
        __syncthreads();          // all threads' stores fenced
        if (tid == 0) atomicAdd(done + byd, 1);
    }
}

// ---------------- split / transpose / reduce / softmax -----------------------
__global__ void __launch_bounds__(256) split2(const float* __restrict__ in,
                                              bf16* __restrict__ hi, bf16* __restrict__ lo,
                                              int n4)
{
    int i = blockIdx.x * 256 + threadIdx.x;
    if (i >= n4) return;
    float4 v = reinterpret_cast<const float4*>(in)[i];
    bf16 h0, l0, h1, l1, h2, l2, h3, l3;
    split1(v.x, h0, l0); split1(v.y, h1, l1); split1(v.z, h2, l2); split1(v.w, h3, l3);
    reinterpret_cast<uint2*>(hi)[i] = make_uint2(pack2(h0, h1), pack2(h2, h3));
    reinterpret_cast<uint2*>(lo)[i] = make_uint2(pack2(l0, l1), pack2(l2, l3));
}

// parts: [4][NCTX*DHEAD] fp32 = {q half0, q half1, k half0, k half1}
__global__ void __launch_bounds__(256) reduce_split(const float* __restrict__ parts,
                                                    bf16* __restrict__ qh, bf16* __restrict__ ql,
                                                    bf16* __restrict__ kh, bf16* __restrict__ kl)
{
    const int o = blockIdx.y;                 // 0 = q, 1 = k
    const int i = blockIdx.x * 256 + threadIdx.x;   // float4 index
    const int n4 = NCTX * DHEAD / 4;
    if (i >= n4) return;
    const float4* p0 = reinterpret_cast<const float4*>(parts + (size_t)o * 2 * NCTX * DHEAD);
    const float4* p1 = p0 + n4;
    float4 a = p0[i], b = p1[i];
    float4 s = make_float4(a.x + b.x, a.y + b.y, a.z + b.z, a.w + b.w);
    bf16 h0, l0, h1, l1, h2, l2, h3, l3;
    split1(s.x, h0, l0); split1(s.y, h1, l1); split1(s.z, h2, l2); split1(s.w, h3, l3);
    bf16* hi = o ? kh : qh;
    bf16* lo = o ? kl : ql;
    reinterpret_cast<uint2*>(hi)[i] = make_uint2(pack2(h0, h1), pack2(h2, h3));
    reinterpret_cast<uint2*>(lo)[i] = make_uint2(pack2(l0, l1), pack2(l2, l3));
}

__global__ void __launch_bounds__(256) transpose_split(const float* __restrict__ in,  // [R, Ccols]
                                                       bf16* __restrict__ tHi, bf16* __restrict__ tLo,
                                                       int R, int Ccols)
{
    __shared__ float t[32][33];
    int c0 = blockIdx.x * 32, r0 = blockIdx.y * 32;
    int tx = threadIdx.x & 31, ty = threadIdx.x >> 5;   // 32 x 8
    #pragma unroll
    for (int j = 0; j < 4; ++j)
        t[ty + 8 * j][tx] = in[(size_t)(r0 + ty + 8 * j) * Ccols + c0 + tx];
    __syncthreads();
    #pragma unroll
    for (int j = 0; j < 4; ++j) {
        float v = t[tx][ty + 8 * j];
        bf16 h, l; split1(v, h, l);
        size_t o = (size_t)(c0 + ty + 8 * j) * R + r0 + tx;
        tHi[o] = h; tLo[o] = l;
    }
}

__device__ __forceinline__ float warpMax(float v) {
    #pragma unroll
    for (int o = 16; o > 0; o >>= 1) v = fmaxf(v, __shfl_xor_sync(0xffffffffu, v, o));
    return v;
}
__device__ __forceinline__ float warpSum(float v) {
    #pragma unroll
    for (int o = 16; o > 0; o >>= 1) v += __shfl_xor_sync(0xffffffffu, v, o);
    return v;
}

// Register-resident causal row softmax: S read ONCE (4 float4/thread), exp
// computed once, P written as hi/lo bf16 (zero-padded to row's 128 boundary).
__global__ void __launch_bounds__(256) softmax_split(const float* __restrict__ S,
                                                     bf16* __restrict__ Ph, bf16* __restrict__ Pl)
{
    const int row    = blockIdx.x;
    const int len    = row + 1;
    const int padLen = (row & ~127) + 128;
    const int nf4    = padLen >> 2;            // float4s to produce (multiple of 32)
    const float* Sr = S + (size_t)row * NCTX;
    bf16* PhR = Ph + (size_t)row * NCTX;
    bf16* PlR = Pl + (size_t)row * NCTX;

    __shared__ float sh[8];
    const int lane = threadIdx.x & 31;
    const int wid  = threadIdx.x >> 5;

    // load row into registers (up to 4 float4 per thread), tracking local max
    float v[4][4];
    float m = -3.4e38f;
    #pragma unroll
    for (int j = 0; j < 4; ++j) {
        const int f4 = threadIdx.x + j * 256;
        const int base = f4 * 4;
        if (f4 < nf4 && base < len) {
            float4 t = *reinterpret_cast<const float4*>(Sr + base);
            v[j][0] = (base + 0 < len) ? t.x : -3.4e38f;
            v[j][1] = (base + 1 < len) ? t.y : -3.4e38f;
            v[j][2] = (base + 2 < len) ? t.z : -3.4e38f;
            v[j][3] = (base + 3 < len) ? t.w : -3.4e38f;
            m = fmaxf(m, fmaxf(fmaxf(v[j][0], v[j][1]), fmaxf(v[j][2], v[j][3])));
        } else {
            v[j][0] = v[j][1] = v[j][2] = v[j][3] = -3.4e38f;
        }
    }
    m = warpMax(m);
    if (lane == 0) sh[wid] = m;
    __syncthreads();
    m = warpMax(lane < 8 ? sh[lane] : -3.4e38f);

    // exp in registers (once), local sum
    float s = 0.f;
    #pragma unroll
    for (int j = 0; j < 4; ++j)
        #pragma unroll
        for (int e = 0; e < 4; ++e) {
            float p = (v[j][e] > -3.0e38f) ? __expf(v[j][e] - m) : 0.f;
            v[j][e] = p;
            s += p;
        }
    s = warpSum(s);
    __syncthreads();
    if (lane == 0) sh[wid] = s;
    __syncthreads();
    s = warpSum(lane < 8 ? sh[lane] : 0.f);

    const float inv = 1.f / s;
    #pragma unroll
    for (int j = 0; j < 4; ++j) {
        const int f4 = threadIdx.x + j * 256;
        if (f4 < nf4) {
            bf16 h0, l0, h1, l1, h2, l2, h3, l3;
            split1(v[j][0] * inv, h0, l0); split1(v[j][1] * inv, h1, l1);
            split1(v[j][2] * inv, h2, l2); split1(v[j][3] * inv, h3, l3);
            *reinterpret_cast<uint2*>(PhR + f4 * 4) = make_uint2(pack2(h0, h1), pack2(h2, h3));
            *reinterpret_cast<uint2*>(PlR + f4 * 4) = make_uint2(pack2(l0, l1), pack2(l2, l3));
        }
    }
}

// ---------------------------------------------------------------------------
extern "C" void kernel_launch(void* const* d_in, const int* in_sizes, int n_in,
                              void* d_out, int out_size)
{
    const float* x  = (const float*)d_in[0];
    const float* Wk = (const float*)d_in[1];
    const float* Wq = (const float*)d_in[2];
    const float* W2 = (const float*)d_in[3];
    float* out = (float*)d_out;

    bf16 *x_hi, *x_lo, *xT_hi, *xT_lo, *Wq_hi, *Wq_lo, *Wk_hi, *Wk_lo, *W2_hi, *W2_lo;
    bf16 *q_hi, *q_lo, *k_hi, *k_lo, *P_hi, *P_lo, *O1_hi, *O1_lo;
    float* S;
    int* done;
    cudaGetSymbolAddress((void**)&x_hi,  g_x_hi);  cudaGetSymbolAddress((void**)&x_lo,  g_x_lo);
    cudaGetSymbolAddress((void**)&xT_hi, g_xT_hi); cudaGetSymbolAddress((void**)&xT_lo, g_xT_lo);
    cudaGetSymbolAddress((void**)&Wq_hi, g_Wq_hi); cudaGetSymbolAddress((void**)&Wq_lo, g_Wq_lo);
    cudaGetSymbolAddress((void**)&Wk_hi, g_Wk_hi); cudaGetSymbolAddress((void**)&Wk_lo, g_Wk_lo);
    cudaGetSymbolAddress((void**)&W2_hi, g_W2_hi); cudaGetSymbolAddress((void**)&W2_lo, g_W2_lo);
    cudaGetSymbolAddress((void**)&q_hi,  g_q_hi);  cudaGetSymbolAddress((void**)&q_lo,  g_q_lo);
    cudaGetSymbolAddress((void**)&k_hi,  g_k_hi);  cudaGetSymbolAddress((void**)&k_lo,  g_k_lo);
    cudaGetSymbolAddress((void**)&P_hi,  g_P_hi);  cudaGetSymbolAddress((void**)&P_lo,  g_P_lo);
    cudaGetSymbolAddress((void**)&O1_hi, g_O1_hi); cudaGetSymbolAddress((void**)&O1_lo, g_O1_lo);
    cudaGetSymbolAddress((void**)&S, g_S);
    cudaGetSymbolAddress((void**)&done, g_done);

    cudaFuncSetAttribute(gemm_mma<0, false, false, true, false>,
                         cudaFuncAttributeMaxDynamicSharedMemorySize, SMEM_TOTAL);
    cudaFuncSetAttribute(gemm_mma<0, true, false, false, false>,
                         cudaFuncAttributeMaxDynamicSharedMemorySize, SMEM_TOTAL);
    cudaFuncSetAttribute(gemm_mma<1, false, false, false, true>,
                         cudaFuncAttributeMaxDynamicSharedMemorySize, SMEM_TOTAL);

    // split inputs to bf16 hi/lo (+ transposed x for the P@x NT GEMM)
    split2<<<(NCTX * DMODEL / 4 + 255) / 256, 256>>>(x, x_hi, x_lo, NCTX * DMODEL / 4);
    split2<<<(DHEAD * DMODEL / 4 + 255) / 256, 256>>>(Wq, Wq_hi, Wq_lo, DHEAD * DMODEL / 4);
    split2<<<(DHEAD * DMODEL / 4 + 255) / 256, 256>>>(Wk, Wk_hi, Wk_lo, DHEAD * DMODEL / 4);
    split2<<<(DMODEL * DMODEL / 4 + 255) / 256, 256>>>(W2, W2_hi, W2_lo, DMODEL * DMODEL / 4);
    transpose_split<<<dim3(DMODEL / 32, NCTX / 32), 256>>>(x, xT_hi, xT_lo, NCTX, DMODEL);

    // 1) fused q/k projection, split-K=2 -> fp32 partials in S scratch, then reduce+split
    gemm_mma<0, false, false, true, false><<<dim3(4, NCTX / 128), 256, SMEM_TOTAL>>>(
        x_hi, x_lo, Wq_hi, Wq_lo, Wk_hi, Wk_lo, nullptr, nullptr,
        S, nullptr, nullptr, NCTX, DHEAD, DMODEL, 0, nullptr);
    reduce_split<<<dim3(NCTX * DHEAD / 4 / 256, 2), 256>>>(S, q_hi, q_lo, k_hi, k_lo);

    // 2) S = q @ k^T -- packed lower-triangle 1D grid (528 CTAs, no dead blocks)
    gemm_mma<0, true, false, false, false><<<dim3(NCTX / 128 * (NCTX / 128 + 1) / 2, 1), 256, SMEM_TOTAL>>>(
        q_hi, q_lo, k_hi, k_lo, nullptr, nullptr, nullptr, nullptr,
        S, nullptr, nullptr, NCTX, NCTX, DHEAD, 0, nullptr);

    // 3) causal softmax (register-resident, single S read) -> P hi/lo
    softmax_split<<<NCTX, 256>>>(S, P_hi, P_lo);

    // 4+5) FUSED: P@x (bids 0..511 -> O1 hi/lo + release) and O1@W2^T (bids
    //      512..1023, spin on row completion -> fp32 out), one 1024-CTA launch.
    cudaMemsetAsync(done, 0, (NCTX / 128) * sizeof(int));
    gemm_mma<1, false, false, false, true><<<dim3(1024, 1), 256, SMEM_TOTAL>>>(
        P_hi, P_lo, xT_hi, xT_lo, W2_hi, W2_lo, O1_hi, O1_lo,
        out, O1_hi, O1_lo, NCTX, DMODEL, NCTX, DMODEL, done);
}